// round 15
// baseline (speedup 1.0000x reference)
#include <cuda_runtime.h>
#include <cuda_fp16.h>
#include <cstdint>

#define NN   4096
#define DIN  128
#define HD   128
#define NE   131072
#define TOTE (NE + NN)
#define NEG  0.2f
#define G4   512
#define NPANEL 32
#define NTILE  (NPANEL * NPANEL)
#define NWORK  115   // tile-worker blocks (bids 33..147)

__device__ float g_h[NN * 512];
__device__ float g_asrc[NN * 4];
__device__ float g_adst[NN * 4];
__device__ int   g_cnt[NN];
__device__ int   g_off[NN + 1];
__device__ int   g_cur[NN];
__device__ int   g_srcs[TOTE];
__device__ float g_g[NN * HD];
__device__ float g_xg[(NN + 1) * G4];   // [t][j], j = gate*128+unit; +1 row slack
__device__ __half g_xa[NN * 384];
__device__ __half g_xb[NN * 384];
__device__ __half g_pa[NN * 384];       // packed activations (x, then g)
__device__ __half g_wb[512 * 384];      // packed weights (Wgat^T, then Wih)
__device__ int   g_prog;                // LSTM progress (emb rows done)
__device__ int   g_packed[NPANEL];      // xn panel packed flags

__device__ __forceinline__ unsigned pack_h2(float x, float y) {
    __half2 h = __floats2half2_rn(x, y);
    return *reinterpret_cast<unsigned*>(&h);
}

__device__ __forceinline__ float tanh_ap(float x) {
    float y;
    asm("tanh.approx.f32 %0, %1;" : "=f"(y) : "f"(x));
    return y;
}

__device__ __forceinline__ void mma16816(float* d, const unsigned* a, unsigned b0, unsigned b1) {
    asm volatile(
        "mma.sync.aligned.m16n8k16.row.col.f32.f16.f16.f32 "
        "{%0,%1,%2,%3}, {%4,%5,%6,%7}, {%8,%9}, {%0,%1,%2,%3};\n"
        : "+f"(d[0]), "+f"(d[1]), "+f"(d[2]), "+f"(d[3])
        : "r"(a[0]), "r"(a[1]), "r"(a[2]), "r"(a[3]), "r"(b0), "r"(b1));
}

__global__ void zero_cnt_kernel() {
    int i = blockIdx.x * blockDim.x + threadIdx.x;
    if (i < NN) g_cnt[i] = 0;
    if (i < NPANEL) g_packed[i] = 0;
    if (i == NPANEL) g_prog = 0;
}

// ---- pack fp32 activations (Mx128) -> split-fp16 (Mx384): [hi, lo, hi] ----
__global__ void pack_a_kernel(const float* __restrict__ src, __half* __restrict__ dst) {
    int n = blockIdx.x, tid = threadIdx.x;
    float v = src[(size_t)n * 128 + tid];
    __half hi = __float2half_rn(v);
    __half lo = __float2half_rn(v - __half2float(hi));
    size_t base = (size_t)n * 384;
    dst[base + tid]       = hi;
    dst[base + 128 + tid] = lo;
    dst[base + 256 + tid] = hi;
}

// ---- pack W^T (W: 128x512) -> (512x384): [hi, hi, lo] ----
__global__ void pack_bT_kernel(const float* __restrict__ W, __half* __restrict__ dst) {
    int j = blockIdx.x, k = threadIdx.x;
    float v = W[(size_t)k * 512 + j];
    __half hi = __float2half_rn(v);
    __half lo = __float2half_rn(v - __half2float(hi));
    size_t base = (size_t)j * 384;
    dst[base + k]       = hi;
    dst[base + 128 + k] = hi;
    dst[base + 256 + k] = lo;
}

// ---- pack W (W: 512x128 row-major) -> (512x384): [hi, hi, lo] ----
__global__ void pack_b_kernel(const float* __restrict__ W, __half* __restrict__ dst) {
    int j = blockIdx.x, k = threadIdx.x;
    float v = W[(size_t)j * 128 + k];
    __half hi = __float2half_rn(v);
    __half lo = __float2half_rn(v - __half2float(hi));
    size_t base = (size_t)j * 384;
    dst[base + k]       = hi;
    dst[base + 128 + k] = hi;
    dst[base + 256 + k] = lo;
}

// ---- HMMA GEMM (prelude GEMMs): C = A(Mx384) @ B(Nx384)^T ----
__global__ __launch_bounds__(256, 2)
void hgemm_kernel(const __half* __restrict__ A, const __half* __restrict__ B,
                  const float* __restrict__ bias, const float* __restrict__ bias2,
                  float* __restrict__ C, int ldc) {
    __shared__ __align__(16) __half As[128 * 24];
    __shared__ __align__(16) __half Bs[128 * 24];
    int tid = threadIdx.x;
    int w = tid >> 5, lane = tid & 31;
    int g = lane >> 2, t2 = (lane & 3) * 2;
    int wm = w >> 2, wn = w & 3;
    int rb = blockIdx.y * 128, cb = blockIdx.x * 128;

    float acc[16][4];
#pragma unroll
    for (int i = 0; i < 16; i++)
#pragma unroll
        for (int q = 0; q < 4; q++) acc[i][q] = 0.f;

    int r = tid >> 1, p = tid & 1;
#pragma unroll 2
    for (int kc = 0; kc < 24; kc++) {
        *reinterpret_cast<uint4*>(&As[r * 24 + p * 8]) =
            *reinterpret_cast<const uint4*>(&A[(size_t)(rb + r) * 384 + kc * 16 + p * 8]);
        *reinterpret_cast<uint4*>(&Bs[r * 24 + p * 8]) =
            *reinterpret_cast<const uint4*>(&B[(size_t)(cb + r) * 384 + kc * 16 + p * 8]);
        __syncthreads();
        unsigned af[4][4], bf[4][2];
#pragma unroll
        for (int mt = 0; mt < 4; mt++) {
            int mb = wm * 64 + mt * 16;
            af[mt][0] = *reinterpret_cast<const unsigned*>(&As[(mb + g)     * 24 + t2]);
            af[mt][1] = *reinterpret_cast<const unsigned*>(&As[(mb + g + 8) * 24 + t2]);
            af[mt][2] = *reinterpret_cast<const unsigned*>(&As[(mb + g)     * 24 + t2 + 8]);
            af[mt][3] = *reinterpret_cast<const unsigned*>(&As[(mb + g + 8) * 24 + t2 + 8]);
        }
#pragma unroll
        for (int nt = 0; nt < 4; nt++) {
            int nb = wn * 32 + nt * 8;
            bf[nt][0] = *reinterpret_cast<const unsigned*>(&Bs[(nb + g) * 24 + t2]);
            bf[nt][1] = *reinterpret_cast<const unsigned*>(&Bs[(nb + g) * 24 + t2 + 8]);
        }
#pragma unroll
        for (int mt = 0; mt < 4; mt++)
#pragma unroll
            for (int nt = 0; nt < 4; nt++)
                mma16816(acc[mt * 4 + nt], af[mt], bf[nt][0], bf[nt][1]);
        __syncthreads();
    }
#pragma unroll
    for (int mt = 0; mt < 4; mt++) {
#pragma unroll
        for (int nt = 0; nt < 4; nt++) {
            int row = rb + wm * 64 + mt * 16 + g;
            int col = cb + wn * 32 + nt * 8 + t2;
            float b0 = 0.f, b1 = 0.f;
            if (bias)  { b0 += bias[col];  b1 += bias[col + 1]; }
            if (bias2) { b0 += bias2[col]; b1 += bias2[col + 1]; }
            float2 v0 = make_float2(acc[mt * 4 + nt][0] + b0, acc[mt * 4 + nt][1] + b1);
            float2 v1 = make_float2(acc[mt * 4 + nt][2] + b0, acc[mt * 4 + nt][3] + b1);
            *reinterpret_cast<float2*>(&C[(size_t)row * ldc + col]) = v0;
            *reinterpret_cast<float2*>(&C[(size_t)(row + 8) * ldc + col]) = v1;
        }
    }
}

// ---- attention logits ----
__global__ void a_kernel(const float* __restrict__ att_src,
                         const float* __restrict__ att_dst) {
    int n = blockIdx.x, tid = threadIdx.x;
    float hv = g_h[(size_t)n * 512 + tid];
    float ps = hv * att_src[tid];
    float pd = hv * att_dst[tid];
#pragma unroll
    for (int o = 16; o > 0; o >>= 1) {
        ps += __shfl_down_sync(0xffffffffu, ps, o);
        pd += __shfl_down_sync(0xffffffffu, pd, o);
    }
    __shared__ float sps[16], spd[16];
    int w = tid >> 5;
    if ((tid & 31) == 0) { sps[w] = ps; spd[w] = pd; }
    __syncthreads();
    if (tid < 4) {
        g_asrc[n * 4 + tid] = sps[tid * 4] + sps[tid * 4 + 1] + sps[tid * 4 + 2] + sps[tid * 4 + 3];
        g_adst[n * 4 + tid] = spd[tid * 4] + spd[tid * 4 + 1] + spd[tid * 4 + 2] + spd[tid * 4 + 3];
    }
}

__global__ void count_kernel(const int* __restrict__ ei) {
    int i = blockIdx.x * blockDim.x + threadIdx.x;
    if (i < NE) atomicAdd(&g_cnt[ei[NE + i]], 1);
    if (i < NN) atomicAdd(&g_cnt[i], 1);
}

__global__ void scan_kernel() {
    __shared__ int s[1024];
    int tid = threadIdx.x;
    int c[4]; int sum = 0;
#pragma unroll
    for (int i = 0; i < 4; i++) { c[i] = g_cnt[tid * 4 + i]; sum += c[i]; }
    s[tid] = sum;
    __syncthreads();
    for (int off = 1; off < 1024; off <<= 1) {
        int v = s[tid];
        int add = (tid >= off) ? s[tid - off] : 0;
        __syncthreads();
        s[tid] = v + add;
        __syncthreads();
    }
    int run = (tid == 0) ? 0 : s[tid - 1];
#pragma unroll
    for (int i = 0; i < 4; i++) {
        g_off[tid * 4 + i] = run;
        g_cur[tid * 4 + i] = run;
        run += c[i];
    }
    if (tid == 1023) g_off[NN] = run;
}

__global__ void scatter_kernel(const int* __restrict__ ei) {
    int i = blockIdx.x * blockDim.x + threadIdx.x;
    if (i < NE) {
        int d = ei[NE + i];
        g_srcs[atomicAdd(&g_cur[d], 1)] = ei[i];
    }
    if (i < NN) g_srcs[atomicAdd(&g_cur[i], 1)] = i;
}

// ---- GAT softmax + aggregate (no-max softmax) ----
#define CHUNK 512
__global__ __launch_bounds__(512)
void gat_agg_kernel(const float* __restrict__ b_gat) {
    int n = blockIdx.x, tid = threadIdx.x;
    int beg = g_off[n], end = g_off[n + 1];
    int deg = end - beg;

    __shared__ int   ssrc[CHUNK];
    __shared__ float salpha[CHUNK * 4];
    __shared__ float red[512];
    __shared__ float rs_sh[4];

    int hh = tid & 3;
    float adst = g_adst[n * 4 + hh];

    float ssum = 0.f;
    for (int e = tid >> 2; e < deg; e += 128) {
        int s = g_srcs[beg + e];
        float v = g_asrc[s * 4 + hh] + adst;
        v = v >= 0.f ? v : NEG * v;
        ssum += __expf(v);
    }
    red[tid] = ssum;
    __syncthreads();
    for (int s = 256; s >= 4; s >>= 1) {
        if (tid < s) red[tid] += red[tid + s];
        __syncthreads();
    }
    if (tid < 4) rs_sh[tid] = 1.0f / (red[tid] + 1e-16f);
    __syncthreads();

    int head = tid >> 7;
    float acc = 0.f;
    float4 ad4 = *reinterpret_cast<const float4*>(&g_adst[n * 4]);
    float r0 = rs_sh[0], r1 = rs_sh[1], r2 = rs_sh[2], r3 = rs_sh[3];

    for (int base = 0; base < deg; base += CHUNK) {
        int cnt = min(CHUNK, deg - base);
        __syncthreads();
        if (tid < cnt) {
            int s = g_srcs[beg + base + tid];
            ssrc[tid] = s;
            float4 as4 = *reinterpret_cast<const float4*>(&g_asrc[s * 4]);
            float e0 = as4.x + ad4.x; e0 = e0 >= 0.f ? e0 : NEG * e0;
            float e1 = as4.y + ad4.y; e1 = e1 >= 0.f ? e1 : NEG * e1;
            float e2 = as4.z + ad4.z; e2 = e2 >= 0.f ? e2 : NEG * e2;
            float e3 = as4.w + ad4.w; e3 = e3 >= 0.f ? e3 : NEG * e3;
            salpha[tid * 4 + 0] = __expf(e0) * r0;
            salpha[tid * 4 + 1] = __expf(e1) * r1;
            salpha[tid * 4 + 2] = __expf(e2) * r2;
            salpha[tid * 4 + 3] = __expf(e3) * r3;
        }
        __syncthreads();
#pragma unroll 4
        for (int e = 0; e < cnt; e++)
            acc += salpha[e * 4 + head] * g_h[(size_t)ssrc[e] * 512 + tid];
    }
    __syncthreads();
    red[tid] = acc;
    __syncthreads();
    if (tid < HD) {
        float s = red[tid] + red[128 + tid] + red[256 + tid] + red[384 + tid];
        float gv = s * 0.25f + b_gat[tid];
        g_g[(size_t)n * HD + tid] = gv > 0.f ? gv : 0.f;
    }
}

// ==== MEGA: block 0 = frozen LSTM (+progress); blocks 1..32 = xn packers;
//      blocks 33..147 = corr tile workers (spin on panel flags). Grid=148 at
//      1 block/SM -> all blocks wave-1 resident -> no deadlock possible. ====
__global__ __launch_bounds__(512, 1)
void mega_kernel(const float* __restrict__ Whh, float* __restrict__ emb_out,
                 float* __restrict__ corrC) {
    int tid = threadIdx.x;

    if (blockIdx.x == 0) {
        // ----- LSTM (r14-frozen + progress publication) -----
        __shared__ __align__(16) __half hsh[128];
        __shared__ float gact[512];
        int j = tid;
        int w = j >> 5, lane = j & 31;
        int g = lane >> 2, t2 = (lane & 3) * 2;
        const bool is_g = (w >= 8 && w < 12);

        unsigned a[2][8][4];
#pragma unroll
        for (int mt = 0; mt < 2; mt++) {
            int rb = w * 32 + mt * 16;
#pragma unroll
            for (int kc = 0; kc < 8; kc++) {
                int cb = kc * 16;
                a[mt][kc][0] = pack_h2(Whh[(size_t)(rb + g)     * 128 + cb + t2],     Whh[(size_t)(rb + g)     * 128 + cb + t2 + 1]);
                a[mt][kc][1] = pack_h2(Whh[(size_t)(rb + g + 8) * 128 + cb + t2],     Whh[(size_t)(rb + g + 8) * 128 + cb + t2 + 1]);
                a[mt][kc][2] = pack_h2(Whh[(size_t)(rb + g)     * 128 + cb + t2 + 8], Whh[(size_t)(rb + g)     * 128 + cb + t2 + 9]);
                a[mt][kc][3] = pack_h2(Whh[(size_t)(rb + g + 8) * 128 + cb + t2 + 8], Whh[(size_t)(rb + g + 8) * 128 + cb + t2 + 9]);
            }
        }
        if (j < 64) reinterpret_cast<__half2*>(hsh)[j] = __floats2half2_rn(0.f, 0.f);
        float c = 0.f;
        __syncthreads();

        float xg = g_xg[j];
#pragma unroll 1
        for (int t = 0; t < NN; t++) {
            float xg_next = g_xg[(size_t)(t + 1) * 512 + j];
            float d0[4] = {0.f, 0.f, 0.f, 0.f};
            float d1[4] = {0.f, 0.f, 0.f, 0.f};
#pragma unroll
            for (int kc = 0; kc < 8; kc++) {
                unsigned b0 = *reinterpret_cast<const unsigned*>(&hsh[kc * 16 + t2]);
                unsigned b1 = *reinterpret_cast<const unsigned*>(&hsh[kc * 16 + t2 + 8]);
                mma16816(d0, a[0][kc], b0, b1);
                mma16816(d1, a[1][kc], b0, b1);
            }
            int src = (lane & 7) * 4;
            float s00 = __shfl_sync(0xffffffffu, d0[0], src);
            float s02 = __shfl_sync(0xffffffffu, d0[2], src);
            float s10 = __shfl_sync(0xffffffffu, d1[0], src);
            float s12 = __shfl_sync(0xffffffffu, d1[2], src);
            float v = (lane & 16) ? ((lane & 8) ? s12 : s10) : ((lane & 8) ? s02 : s00);
            float z = v + xg;
            float act;
            if (is_g) act = tanh_ap(z);
            else      act = fmaf(0.5f, tanh_ap(0.5f * z), 0.5f);
            gact[j] = act;
            __syncthreads();
            if (j < HD) {
                float gi = gact[j], gf = gact[128 + j], gg = gact[256 + j], go = gact[384 + j];
                c = gf * c + gi * gg;
                float hn = go * tanh_ap(c);
                emb_out[(size_t)t * HD + j] = hn;
                hsh[j] = __float2half_rn(hn);
            }
            if ((t & 127) == 127 && j < HD) __threadfence();
            __syncthreads();
            if ((t & 127) == 127 && j == 0) atomicExch(&g_prog, t + 1);
            xg = xg_next;
        }
    } else if (blockIdx.x <= NPANEL) {
        // ----- panel packer: normalize + split-fp16 pack 128 emb rows -----
        int p = blockIdx.x - 1;
        if (tid == 0) {
            while (*(volatile int*)&g_prog < (p + 1) * 128) __nanosleep(1024);
        }
        __syncthreads();
        __threadfence();

        __shared__ float sw[4][5];
        __shared__ float rsh[4];
        int g4 = tid >> 7, sub = tid & 127;
        int wig = (tid >> 5) & 3;
#pragma unroll 1
        for (int it = 0; it < 32; it++) {
            int row = p * 128 + it * 4 + g4;
            float v = emb_out[(size_t)row * HD + sub];
            float ss = v * v;
#pragma unroll
            for (int o = 16; o > 0; o >>= 1) ss += __shfl_down_sync(0xffffffffu, ss, o);
            if ((sub & 31) == 0) sw[g4][wig] = ss;
            __syncthreads();
            if (sub == 0)
                rsh[g4] = 1.0f / fmaxf(sqrtf(sw[g4][0] + sw[g4][1] + sw[g4][2] + sw[g4][3]), 1e-12f);
            __syncthreads();
            float xv = v * rsh[g4];
            __half hi = __float2half_rn(xv);
            __half lo = __float2half_rn(xv - __half2float(hi));
            size_t base = (size_t)row * 384;
            g_xa[base + sub]       = hi;
            g_xa[base + 128 + sub] = lo;
            g_xa[base + 256 + sub] = hi;
            g_xb[base + sub]       = hi;
            g_xb[base + 128 + sub] = hi;
            g_xb[base + 256 + sub] = lo;
            __syncthreads();
        }
        __threadfence();
        __syncthreads();
        if (tid == 0) atomicExch(&g_packed[p], 1);
    } else {
        // ----- corr tile worker: tiles in readiness order (by max panel) -----
        __shared__ __align__(16) __half As[128 * 24];
        __shared__ __align__(16) __half Bs[128 * 24];
        int widx = blockIdx.x - (NPANEL + 1);
        int w = tid >> 5, lane = tid & 31;
        int gq = lane >> 2, t2 = (lane & 3) * 2;
        int wm = w >> 2, wn = w & 3;
        int rr = tid >> 1, pp = tid & 1;

#pragma unroll 1
        for (int k = widx; k < NTILE; k += NWORK) {
            int m = (int)sqrtf((float)k);
            while ((m + 1) * (m + 1) <= k) m++;
            while (m * m > k) m--;
            int r = k - m * m;
            int pi = (r <= m) ? r : m;
            int pj = (r <= m) ? m : (r - m - 1);
            if (tid == 0) {
                while (*(volatile int*)&g_packed[pi] == 0) __nanosleep(1024);
                while (*(volatile int*)&g_packed[pj] == 0) __nanosleep(1024);
            }
            __syncthreads();
            __threadfence();

            int rb = pi * 128, cb = pj * 128;
            float acc[8][4];
#pragma unroll
            for (int i = 0; i < 8; i++)
#pragma unroll
                for (int q = 0; q < 4; q++) acc[i][q] = 0.f;

#pragma unroll 1
            for (int kc = 0; kc < 24; kc++) {
                if (tid < 256) {
                    *reinterpret_cast<uint4*>(&As[rr * 24 + pp * 8]) =
                        *reinterpret_cast<const uint4*>(&g_xa[(size_t)(rb + rr) * 384 + kc * 16 + pp * 8]);
                    *reinterpret_cast<uint4*>(&Bs[rr * 24 + pp * 8]) =
                        *reinterpret_cast<const uint4*>(&g_xb[(size_t)(cb + rr) * 384 + kc * 16 + pp * 8]);
                }
                __syncthreads();
                unsigned af[2][4], bf[4][2];
#pragma unroll
                for (int mt = 0; mt < 2; mt++) {
                    int mb = wm * 32 + mt * 16;
                    af[mt][0] = *reinterpret_cast<const unsigned*>(&As[(mb + gq)     * 24 + t2]);
                    af[mt][1] = *reinterpret_cast<const unsigned*>(&As[(mb + gq + 8) * 24 + t2]);
                    af[mt][2] = *reinterpret_cast<const unsigned*>(&As[(mb + gq)     * 24 + t2 + 8]);
                    af[mt][3] = *reinterpret_cast<const unsigned*>(&As[(mb + gq + 8) * 24 + t2 + 8]);
                }
#pragma unroll
                for (int nt = 0; nt < 4; nt++) {
                    int nb = wn * 32 + nt * 8;
                    bf[nt][0] = *reinterpret_cast<const unsigned*>(&Bs[(nb + gq) * 24 + t2]);
                    bf[nt][1] = *reinterpret_cast<const unsigned*>(&Bs[(nb + gq) * 24 + t2 + 8]);
                }
#pragma unroll
                for (int mt = 0; mt < 2; mt++)
#pragma unroll
                    for (int nt = 0; nt < 4; nt++)
                        mma16816(acc[mt * 4 + nt], af[mt], bf[nt][0], bf[nt][1]);
                __syncthreads();
            }
#pragma unroll
            for (int mt = 0; mt < 2; mt++) {
#pragma unroll
                for (int nt = 0; nt < 4; nt++) {
                    int row = rb + wm * 32 + mt * 16 + gq;
                    int col = cb + wn * 32 + nt * 8 + t2;
                    float2 v0 = make_float2(acc[mt * 4 + nt][0], acc[mt * 4 + nt][1]);
                    float2 v1 = make_float2(acc[mt * 4 + nt][2], acc[mt * 4 + nt][3]);
                    __stcs(reinterpret_cast<float2*>(&corrC[(size_t)row * NN + col]), v0);
                    __stcs(reinterpret_cast<float2*>(&corrC[(size_t)(row + 8) * NN + col]), v1);
                }
            }
            __syncthreads();
        }
    }
}

// ---- MLP head ----
__global__ void mlp_kernel(const float* __restrict__ emb,
                           const float* __restrict__ W1, const float* __restrict__ b1,
                           const float* __restrict__ W2, const float* __restrict__ b2,
                           float* __restrict__ mu, float* __restrict__ sigma) {
    int n = blockIdx.x, tid = threadIdx.x;
    __shared__ float se[128], sh[32];
    se[tid] = emb[(size_t)n * HD + tid];
    __syncthreads();
    if (tid < 32) {
        float a = b1[tid];
#pragma unroll 8
        for (int k = 0; k < 128; k++) a += se[k] * W1[k * 32 + tid];
        sh[tid] = a > 0.f ? a : 0.f;
    }
    __syncthreads();
    if (tid < 2) {
        float a = b2[tid];
#pragma unroll
        for (int k = 0; k < 32; k++) a += sh[k] * W2[k * 2 + tid];
        if (tid == 0) mu[n] = a; else sigma[n] = a;
    }
}

extern "C" void kernel_launch(void* const* d_in, const int* in_sizes, int n_in,
                              void* d_out, int out_size) {
    const float* x       = (const float*)d_in[0];
    const int*   ei      = (const int*)  d_in[1];
    const float* W_gat   = (const float*)d_in[2];
    const float* att_src = (const float*)d_in[3];
    const float* att_dst = (const float*)d_in[4];
    const float* b_gat   = (const float*)d_in[5];
    const float* W_ih    = (const float*)d_in[6];
    const float* W_hh    = (const float*)d_in[7];
    const float* b_ih    = (const float*)d_in[8];
    const float* b_hh    = (const float*)d_in[9];
    const float* W1      = (const float*)d_in[10];
    const float* b1      = (const float*)d_in[11];
    const float* W2      = (const float*)d_in[12];
    const float* b2      = (const float*)d_in[13];
    float* out = (float*)d_out;

    float* emb   = out;
    float* corr  = out + (size_t)NN * HD;
    float* mu    = corr + (size_t)NN * NN;
    float* sigma = mu + NN;

    void *p_h, *p_g, *p_xg, *p_pa, *p_wb;
    cudaGetSymbolAddress(&p_h,  g_h);
    cudaGetSymbolAddress(&p_g,  g_g);
    cudaGetSymbolAddress(&p_xg, g_xg);
    cudaGetSymbolAddress(&p_pa, g_pa);
    cudaGetSymbolAddress(&p_wb, g_wb);

    zero_cnt_kernel<<<(NN + 255) / 256, 256>>>();

    // h = x @ W_gat via split-fp16 HMMA
    pack_a_kernel<<<NN, 128>>>(x, (__half*)p_pa);
    pack_bT_kernel<<<512, 128>>>(W_gat, (__half*)p_wb);
    hgemm_kernel<<<dim3(512 / 128, NN / 128), 256>>>(
        (const __half*)p_pa, (const __half*)p_wb, nullptr, nullptr, (float*)p_h, 512);

    a_kernel<<<NN, 512>>>(att_src, att_dst);

    count_kernel<<<(NE + 255) / 256, 256>>>(ei);
    scan_kernel<<<1, 1024>>>();
    scatter_kernel<<<(NE + 255) / 256, 256>>>(ei);

    gat_agg_kernel<<<NN, 512>>>(b_gat);

    // XG = g @ W_ih^T + b_ih + b_hh via split-fp16 HMMA
    pack_a_kernel<<<NN, 128>>>((const float*)p_g, (__half*)p_pa);
    pack_b_kernel<<<512, 128>>>(W_ih, (__half*)p_wb);
    hgemm_kernel<<<dim3(512 / 128, NN / 128), 256>>>(
        (const __half*)p_pa, (const __half*)p_wb, b_ih, b_hh, (float*)p_xg, 512);

    // LSTM + overlapped xn-pack + corr in one resident mega-kernel
    mega_kernel<<<1 + NPANEL + NWORK, 512>>>(W_hh, emb, corr);

    mlp_kernel<<<NN, 128>>>(emb, W1, b1, W2, b2, mu, sigma);
}

// round 16
// speedup vs baseline: 1.1325x; 1.1325x over previous
#include <cuda_runtime.h>
#include <cuda_fp16.h>
#include <cstdint>

#define NN   4096
#define DIN  128
#define HD   128
#define NE   131072
#define TOTE (NE + NN)
#define NEG  0.2f
#define G4   512

__device__ float g_h[NN * 512];
__device__ float g_asrc[NN * 4];
__device__ float g_adst[NN * 4];
__device__ int   g_cnt[NN];
__device__ int   g_off[NN + 1];
__device__ int   g_cur[NN];
__device__ int   g_srcs[TOTE];
__device__ float g_g[NN * HD];
__device__ float g_xg[(NN + 1) * G4];   // [t][j]; non-g rows pre-scaled by 0.5
__device__ __half g_xa[NN * 384];
__device__ __half g_xb[NN * 384];
__device__ __half g_pa[NN * 384];       // packed activations (x, then g)
__device__ __half g_wb[512 * 384];      // packed weights (Wgat^T, then Wih)

__device__ __forceinline__ unsigned pack_h2(float x, float y) {
    __half2 h = __floats2half2_rn(x, y);
    return *reinterpret_cast<unsigned*>(&h);
}

__device__ __forceinline__ float tanh_ap(float x) {
    float y;
    asm("tanh.approx.f32 %0, %1;" : "=f"(y) : "f"(x));
    return y;
}

__device__ __forceinline__ void mma16816(float* d, const unsigned* a, unsigned b0, unsigned b1) {
    asm volatile(
        "mma.sync.aligned.m16n8k16.row.col.f32.f16.f16.f32 "
        "{%0,%1,%2,%3}, {%4,%5,%6,%7}, {%8,%9}, {%0,%1,%2,%3};\n"
        : "+f"(d[0]), "+f"(d[1]), "+f"(d[2]), "+f"(d[3])
        : "r"(a[0]), "r"(a[1]), "r"(a[2]), "r"(a[3]), "r"(b0), "r"(b1));
}

__global__ void zero_cnt_kernel() {
    int i = blockIdx.x * blockDim.x + threadIdx.x;
    if (i < NN) g_cnt[i] = 0;
}

// ---- pack fp32 activations (Mx128) -> split-fp16 (Mx384): [hi, lo, hi] ----
__global__ void pack_a_kernel(const float* __restrict__ src, __half* __restrict__ dst) {
    int n = blockIdx.x, tid = threadIdx.x;
    float v = src[(size_t)n * 128 + tid];
    __half hi = __float2half_rn(v);
    __half lo = __float2half_rn(v - __half2float(hi));
    size_t base = (size_t)n * 384;
    dst[base + tid]       = hi;
    dst[base + 128 + tid] = lo;
    dst[base + 256 + tid] = hi;
}

// ---- pack W^T (W: 128x512) -> (512x384): [hi, hi, lo] ----
__global__ void pack_bT_kernel(const float* __restrict__ W, __half* __restrict__ dst) {
    int j = blockIdx.x, k = threadIdx.x;
    float v = W[(size_t)k * 512 + j];
    __half hi = __float2half_rn(v);
    __half lo = __float2half_rn(v - __half2float(hi));
    size_t base = (size_t)j * 384;
    dst[base + k]       = hi;
    dst[base + 128 + k] = hi;
    dst[base + 256 + k] = lo;
}

// ---- pack W (W: 512x128 row-major) -> (512x384): [hi, hi, lo] ----
__global__ void pack_b_kernel(const float* __restrict__ W, __half* __restrict__ dst) {
    int j = blockIdx.x, k = threadIdx.x;
    float v = W[(size_t)j * 128 + k];
    __half hi = __float2half_rn(v);
    __half lo = __float2half_rn(v - __half2float(hi));
    size_t base = (size_t)j * 384;
    dst[base + k]       = hi;
    dst[base + 128 + k] = hi;
    dst[base + 256 + k] = lo;
}

// ---- HMMA GEMM: C = A(Mx384) @ B(Nx384)^T; optional bias; optional 0.5x scale
//      of (acc+bias) for gate columns != 2 (halfmask, XG only) ----
__global__ __launch_bounds__(256, 2)
void hgemm_kernel(const __half* __restrict__ A, const __half* __restrict__ B,
                  const float* __restrict__ bias, const float* __restrict__ bias2,
                  float* __restrict__ C, int ldc, int halfmask) {
    __shared__ __align__(16) __half As[128 * 24];
    __shared__ __align__(16) __half Bs[128 * 24];
    int tid = threadIdx.x;
    int w = tid >> 5, lane = tid & 31;
    int g = lane >> 2, t2 = (lane & 3) * 2;
    int wm = w >> 2, wn = w & 3;
    int rb = blockIdx.y * 128, cb = blockIdx.x * 128;

    float acc[16][4];
#pragma unroll
    for (int i = 0; i < 16; i++)
#pragma unroll
        for (int q = 0; q < 4; q++) acc[i][q] = 0.f;

    int r = tid >> 1, p = tid & 1;
#pragma unroll 2
    for (int kc = 0; kc < 24; kc++) {
        *reinterpret_cast<uint4*>(&As[r * 24 + p * 8]) =
            *reinterpret_cast<const uint4*>(&A[(size_t)(rb + r) * 384 + kc * 16 + p * 8]);
        *reinterpret_cast<uint4*>(&Bs[r * 24 + p * 8]) =
            *reinterpret_cast<const uint4*>(&B[(size_t)(cb + r) * 384 + kc * 16 + p * 8]);
        __syncthreads();
        unsigned af[4][4], bf[4][2];
#pragma unroll
        for (int mt = 0; mt < 4; mt++) {
            int mb = wm * 64 + mt * 16;
            af[mt][0] = *reinterpret_cast<const unsigned*>(&As[(mb + g)     * 24 + t2]);
            af[mt][1] = *reinterpret_cast<const unsigned*>(&As[(mb + g + 8) * 24 + t2]);
            af[mt][2] = *reinterpret_cast<const unsigned*>(&As[(mb + g)     * 24 + t2 + 8]);
            af[mt][3] = *reinterpret_cast<const unsigned*>(&As[(mb + g + 8) * 24 + t2 + 8]);
        }
#pragma unroll
        for (int nt = 0; nt < 4; nt++) {
            int nb = wn * 32 + nt * 8;
            bf[nt][0] = *reinterpret_cast<const unsigned*>(&Bs[(nb + g) * 24 + t2]);
            bf[nt][1] = *reinterpret_cast<const unsigned*>(&Bs[(nb + g) * 24 + t2 + 8]);
        }
#pragma unroll
        for (int mt = 0; mt < 4; mt++)
#pragma unroll
            for (int nt = 0; nt < 4; nt++)
                mma16816(acc[mt * 4 + nt], af[mt], bf[nt][0], bf[nt][1]);
        __syncthreads();
    }
#pragma unroll
    for (int mt = 0; mt < 4; mt++) {
#pragma unroll
        for (int nt = 0; nt < 4; nt++) {
            int row = rb + wm * 64 + mt * 16 + g;
            int col = cb + wn * 32 + nt * 8 + t2;
            float b0 = 0.f, b1 = 0.f;
            if (bias)  { b0 += bias[col];  b1 += bias[col + 1]; }
            if (bias2) { b0 += bias2[col]; b1 += bias2[col + 1]; }
            float sc = (halfmask && ((col >> 7) != 2)) ? 0.5f : 1.0f;
            float2 v0 = make_float2((acc[mt * 4 + nt][0] + b0) * sc, (acc[mt * 4 + nt][1] + b1) * sc);
            float2 v1 = make_float2((acc[mt * 4 + nt][2] + b0) * sc, (acc[mt * 4 + nt][3] + b1) * sc);
            *reinterpret_cast<float2*>(&C[(size_t)row * ldc + col]) = v0;
            *reinterpret_cast<float2*>(&C[(size_t)(row + 8) * ldc + col]) = v1;
        }
    }
}

// ---- attention logits ----
__global__ void a_kernel(const float* __restrict__ att_src,
                         const float* __restrict__ att_dst) {
    int n = blockIdx.x, tid = threadIdx.x;
    float hv = g_h[(size_t)n * 512 + tid];
    float ps = hv * att_src[tid];
    float pd = hv * att_dst[tid];
#pragma unroll
    for (int o = 16; o > 0; o >>= 1) {
        ps += __shfl_down_sync(0xffffffffu, ps, o);
        pd += __shfl_down_sync(0xffffffffu, pd, o);
    }
    __shared__ float sps[16], spd[16];
    int w = tid >> 5;
    if ((tid & 31) == 0) { sps[w] = ps; spd[w] = pd; }
    __syncthreads();
    if (tid < 4) {
        g_asrc[n * 4 + tid] = sps[tid * 4] + sps[tid * 4 + 1] + sps[tid * 4 + 2] + sps[tid * 4 + 3];
        g_adst[n * 4 + tid] = spd[tid * 4] + spd[tid * 4 + 1] + spd[tid * 4 + 2] + spd[tid * 4 + 3];
    }
}

__global__ void count_kernel(const int* __restrict__ ei) {
    int i = blockIdx.x * blockDim.x + threadIdx.x;
    if (i < NE) atomicAdd(&g_cnt[ei[NE + i]], 1);
    if (i < NN) atomicAdd(&g_cnt[i], 1);
}

__global__ void scan_kernel() {
    __shared__ int s[1024];
    int tid = threadIdx.x;
    int c[4]; int sum = 0;
#pragma unroll
    for (int i = 0; i < 4; i++) { c[i] = g_cnt[tid * 4 + i]; sum += c[i]; }
    s[tid] = sum;
    __syncthreads();
    for (int off = 1; off < 1024; off <<= 1) {
        int v = s[tid];
        int add = (tid >= off) ? s[tid - off] : 0;
        __syncthreads();
        s[tid] = v + add;
        __syncthreads();
    }
    int run = (tid == 0) ? 0 : s[tid - 1];
#pragma unroll
    for (int i = 0; i < 4; i++) {
        g_off[tid * 4 + i] = run;
        g_cur[tid * 4 + i] = run;
        run += c[i];
    }
    if (tid == 1023) g_off[NN] = run;
}

__global__ void scatter_kernel(const int* __restrict__ ei) {
    int i = blockIdx.x * blockDim.x + threadIdx.x;
    if (i < NE) {
        int d = ei[NE + i];
        g_srcs[atomicAdd(&g_cur[d], 1)] = ei[i];
    }
    if (i < NN) g_srcs[atomicAdd(&g_cur[i], 1)] = i;
}

// ---- GAT softmax + aggregate (no-max softmax) ----
#define CHUNK 512
__global__ __launch_bounds__(512)
void gat_agg_kernel(const float* __restrict__ b_gat) {
    int n = blockIdx.x, tid = threadIdx.x;
    int beg = g_off[n], end = g_off[n + 1];
    int deg = end - beg;

    __shared__ int   ssrc[CHUNK];
    __shared__ float salpha[CHUNK * 4];
    __shared__ float red[512];
    __shared__ float rs_sh[4];

    int hh = tid & 3;
    float adst = g_adst[n * 4 + hh];

    float ssum = 0.f;
    for (int e = tid >> 2; e < deg; e += 128) {
        int s = g_srcs[beg + e];
        float v = g_asrc[s * 4 + hh] + adst;
        v = v >= 0.f ? v : NEG * v;
        ssum += __expf(v);
    }
    red[tid] = ssum;
    __syncthreads();
    for (int s = 256; s >= 4; s >>= 1) {
        if (tid < s) red[tid] += red[tid + s];
        __syncthreads();
    }
    if (tid < 4) rs_sh[tid] = 1.0f / (red[tid] + 1e-16f);
    __syncthreads();

    int head = tid >> 7;
    float acc = 0.f;
    float4 ad4 = *reinterpret_cast<const float4*>(&g_adst[n * 4]);
    float r0 = rs_sh[0], r1 = rs_sh[1], r2 = rs_sh[2], r3 = rs_sh[3];

    for (int base = 0; base < deg; base += CHUNK) {
        int cnt = min(CHUNK, deg - base);
        __syncthreads();
        if (tid < cnt) {
            int s = g_srcs[beg + base + tid];
            ssrc[tid] = s;
            float4 as4 = *reinterpret_cast<const float4*>(&g_asrc[s * 4]);
            float e0 = as4.x + ad4.x; e0 = e0 >= 0.f ? e0 : NEG * e0;
            float e1 = as4.y + ad4.y; e1 = e1 >= 0.f ? e1 : NEG * e1;
            float e2 = as4.z + ad4.z; e2 = e2 >= 0.f ? e2 : NEG * e2;
            float e3 = as4.w + ad4.w; e3 = e3 >= 0.f ? e3 : NEG * e3;
            salpha[tid * 4 + 0] = __expf(e0) * r0;
            salpha[tid * 4 + 1] = __expf(e1) * r1;
            salpha[tid * 4 + 2] = __expf(e2) * r2;
            salpha[tid * 4 + 3] = __expf(e3) * r3;
        }
        __syncthreads();
#pragma unroll 4
        for (int e = 0; e < cnt; e++)
            acc += salpha[e * 4 + head] * g_h[(size_t)ssrc[e] * 512 + tid];
    }
    __syncthreads();
    red[tid] = acc;
    __syncthreads();
    if (tid < HD) {
        float s = red[tid] + red[128 + tid] + red[256 + tid] + red[384 + tid];
        float gv = s * 0.25f + b_gat[tid];
        g_g[(size_t)n * HD + tid] = gv > 0.f ? gv : 0.f;
    }
}

// ---- LSTM: r14-frozen structure; non-g weights & xg pre-scaled by 0.5 so the
//      sigmoid path is fmaf(0.5, tanh(z'), 0.5) with no pre-MUFU FMUL ----
__global__ __launch_bounds__(512, 1)
void lstm_kernel(const float* __restrict__ Whh, float* __restrict__ emb_out) {
    __shared__ __align__(16) __half hsh[128];
    __shared__ float gact[512];
    int j = threadIdx.x;
    int w = j >> 5, lane = j & 31;
    int g = lane >> 2, t2 = (lane & 3) * 2;
    const bool is_g = (w >= 8 && w < 12);
    const float ws = is_g ? 1.0f : 0.5f;

    unsigned a[2][8][4];
#pragma unroll
    for (int mt = 0; mt < 2; mt++) {
        int rb = w * 32 + mt * 16;
#pragma unroll
        for (int kc = 0; kc < 8; kc++) {
            int cb = kc * 16;
            a[mt][kc][0] = pack_h2(ws * Whh[(size_t)(rb + g)     * 128 + cb + t2],     ws * Whh[(size_t)(rb + g)     * 128 + cb + t2 + 1]);
            a[mt][kc][1] = pack_h2(ws * Whh[(size_t)(rb + g + 8) * 128 + cb + t2],     ws * Whh[(size_t)(rb + g + 8) * 128 + cb + t2 + 1]);
            a[mt][kc][2] = pack_h2(ws * Whh[(size_t)(rb + g)     * 128 + cb + t2 + 8], ws * Whh[(size_t)(rb + g)     * 128 + cb + t2 + 9]);
            a[mt][kc][3] = pack_h2(ws * Whh[(size_t)(rb + g + 8) * 128 + cb + t2 + 8], ws * Whh[(size_t)(rb + g + 8) * 128 + cb + t2 + 9]);
        }
    }
    if (j < 64) reinterpret_cast<__half2*>(hsh)[j] = __floats2half2_rn(0.f, 0.f);
    float c = 0.f;
    __syncthreads();

    float xg = g_xg[j];
#pragma unroll 1
    for (int t = 0; t < NN; t++) {
        float xg_next = g_xg[(size_t)(t + 1) * 512 + j];
        float d0[4] = {0.f, 0.f, 0.f, 0.f};
        float d1[4] = {0.f, 0.f, 0.f, 0.f};
#pragma unroll
        for (int kc = 0; kc < 8; kc++) {
            unsigned b0 = *reinterpret_cast<const unsigned*>(&hsh[kc * 16 + t2]);
            unsigned b1 = *reinterpret_cast<const unsigned*>(&hsh[kc * 16 + t2 + 8]);
            mma16816(d0, a[0][kc], b0, b1);
            mma16816(d1, a[1][kc], b0, b1);
        }
        int src = (lane & 7) * 4;
        float s00 = __shfl_sync(0xffffffffu, d0[0], src);
        float s02 = __shfl_sync(0xffffffffu, d0[2], src);
        float s10 = __shfl_sync(0xffffffffu, d1[0], src);
        float s12 = __shfl_sync(0xffffffffu, d1[2], src);
        float v = (lane & 16) ? ((lane & 8) ? s12 : s10) : ((lane & 8) ? s02 : s00);
        float z = v + xg;
        float act;
        if (is_g) act = tanh_ap(z);
        else      act = fmaf(0.5f, tanh_ap(z), 0.5f);
        gact[j] = act;
        __syncthreads();
        if (j < HD) {
            float gi = gact[j], gf = gact[128 + j], gg = gact[256 + j], go = gact[384 + j];
            c = gf * c + gi * gg;
            float hn = go * tanh_ap(c);
            emb_out[(size_t)t * HD + j] = hn;
            hsh[j] = __float2half_rn(hn);
        }
        __syncthreads();
        xg = xg_next;
    }
}

// ---- normalize + pack split-fp16 for corr ----
__global__ void xn_pack_kernel(const float* __restrict__ emb) {
    int n = blockIdx.x, tid = threadIdx.x;
    float v = emb[(size_t)n * HD + tid];
    float ss = v * v;
#pragma unroll
    for (int o = 16; o > 0; o >>= 1) ss += __shfl_down_sync(0xffffffffu, ss, o);
    __shared__ float sw[4];
    __shared__ float rsh;
    if ((tid & 31) == 0) sw[tid >> 5] = ss;
    __syncthreads();
    if (tid == 0) rsh = 1.0f / fmaxf(sqrtf(sw[0] + sw[1] + sw[2] + sw[3]), 1e-12f);
    __syncthreads();
    float xv = v * rsh;
    __half hi = __float2half_rn(xv);
    __half lo = __float2half_rn(xv - __half2float(hi));
    size_t base = (size_t)n * 384;
    g_xa[base + tid]       = hi;
    g_xa[base + 128 + tid] = lo;
    g_xa[base + 256 + tid] = hi;
    g_xb[base + tid]       = hi;
    g_xb[base + 128 + tid] = hi;
    g_xb[base + 256 + tid] = lo;
}

// ---- MLP head ----
__global__ void mlp_kernel(const float* __restrict__ emb,
                           const float* __restrict__ W1, const float* __restrict__ b1,
                           const float* __restrict__ W2, const float* __restrict__ b2,
                           float* __restrict__ mu, float* __restrict__ sigma) {
    int n = blockIdx.x, tid = threadIdx.x;
    __shared__ float se[128], sh[32];
    se[tid] = emb[(size_t)n * HD + tid];
    __syncthreads();
    if (tid < 32) {
        float a = b1[tid];
#pragma unroll 8
        for (int k = 0; k < 128; k++) a += se[k] * W1[k * 32 + tid];
        sh[tid] = a > 0.f ? a : 0.f;
    }
    __syncthreads();
    if (tid < 2) {
        float a = b2[tid];
#pragma unroll
        for (int k = 0; k < 32; k++) a += sh[k] * W2[k * 2 + tid];
        if (tid == 0) mu[n] = a; else sigma[n] = a;
    }
}

extern "C" void kernel_launch(void* const* d_in, const int* in_sizes, int n_in,
                              void* d_out, int out_size) {
    const float* x       = (const float*)d_in[0];
    const int*   ei      = (const int*)  d_in[1];
    const float* W_gat   = (const float*)d_in[2];
    const float* att_src = (const float*)d_in[3];
    const float* att_dst = (const float*)d_in[4];
    const float* b_gat   = (const float*)d_in[5];
    const float* W_ih    = (const float*)d_in[6];
    const float* W_hh    = (const float*)d_in[7];
    const float* b_ih    = (const float*)d_in[8];
    const float* b_hh    = (const float*)d_in[9];
    const float* W1      = (const float*)d_in[10];
    const float* b1      = (const float*)d_in[11];
    const float* W2      = (const float*)d_in[12];
    const float* b2      = (const float*)d_in[13];
    float* out = (float*)d_out;

    float* emb   = out;
    float* corr  = out + (size_t)NN * HD;
    float* mu    = corr + (size_t)NN * NN;
    float* sigma = mu + NN;

    void *p_h, *p_g, *p_xg, *p_pa, *p_wb, *p_xa, *p_xb;
    cudaGetSymbolAddress(&p_h,  g_h);
    cudaGetSymbolAddress(&p_g,  g_g);
    cudaGetSymbolAddress(&p_xg, g_xg);
    cudaGetSymbolAddress(&p_pa, g_pa);
    cudaGetSymbolAddress(&p_wb, g_wb);
    cudaGetSymbolAddress(&p_xa, g_xa);
    cudaGetSymbolAddress(&p_xb, g_xb);

    zero_cnt_kernel<<<(NN + 255) / 256, 256>>>();

    // h = x @ W_gat via split-fp16 HMMA
    pack_a_kernel<<<NN, 128>>>(x, (__half*)p_pa);
    pack_bT_kernel<<<512, 128>>>(W_gat, (__half*)p_wb);
    hgemm_kernel<<<dim3(512 / 128, NN / 128), 256>>>(
        (const __half*)p_pa, (const __half*)p_wb, nullptr, nullptr, (float*)p_h, 512, 0);

    a_kernel<<<NN, 512>>>(att_src, att_dst);

    count_kernel<<<(NE + 255) / 256, 256>>>(ei);
    scan_kernel<<<1, 1024>>>();
    scatter_kernel<<<(NE + 255) / 256, 256>>>(ei);

    gat_agg_kernel<<<NN, 512>>>(b_gat);

    // XG = (g @ W_ih^T + b_ih + b_hh), non-g gate rows pre-scaled by 0.5
    pack_a_kernel<<<NN, 128>>>((const float*)p_g, (__half*)p_pa);
    pack_b_kernel<<<512, 128>>>(W_ih, (__half*)p_wb);
    hgemm_kernel<<<dim3(512 / 128, NN / 128), 256>>>(
        (const __half*)p_pa, (const __half*)p_wb, b_ih, b_hh, (float*)p_xg, 512, 1);

    lstm_kernel<<<1, 512>>>(W_hh, emb);

    xn_pack_kernel<<<NN, 128>>>(emb);

    // corr = xa @ xb^T
    hgemm_kernel<<<dim3(NN / 128, NN / 128), 256>>>(
        (const __half*)p_xa, (const __half*)p_xb, nullptr, nullptr, corr, NN, 0);

    mlp_kernel<<<NN, 128>>>(emb, W1, b1, W2, b2, mu, sigma);
}